// round 5
// baseline (speedup 1.0000x reference)
#include <cuda_runtime.h>
#include <cstdint>
#include <math.h>

// Problem constants
#define T_   4096
#define B_   8
#define D_   512
#define H_   8
#define BS_  64
#define NB_  64
#define DH_  64
#define M_   (T_*B_)    // 32768 rows
#define BD_  (B_*D_)    // 4096
#define K3D  (3*D_)     // 1536
#define K3H  (3*2*D_)   // 3072

// ---------------- scratch (static device globals; no allocations) ----------
__device__ float g_xc   [M_*D_];        // conv+bn output (residual for O-gemm)
__device__ float g_xc3  [M_*K3D];       // split3 of xc; later reused for x13
__device__ float g_attn3[M_*K3D];       // split3 of attention output
__device__ float g_hbuf3[M_*K3H];       // split3 of gelu(MLP1)
__device__ float g_q    [M_*D_];
__device__ float g_k    [M_*D_];
__device__ float g_v    [M_*D_];
__device__ float g_x1   [M_*D_];
__device__ float g_tmp  [M_*D_];
// transposed + split weights [N, 3K]
__device__ float g_wt3q [D_*K3D];
__device__ float g_wt3k [D_*K3D];
__device__ float g_wt3v [D_*K3D];
__device__ float g_wt3o [D_*K3D];
__device__ float g_wt31 [2*D_*K3D];     // [1024, 1536]
__device__ float g_wt32 [D_*K3H];       // [512, 3072]

// ---------------- helpers ---------------------------------------------------
__device__ __forceinline__ void tf32_split(float x, float& hi, float& lo) {
    uint32_t hb;
    asm("cvt.rna.tf32.f32 %0, %1;" : "=r"(hb) : "f"(x));
    hi = __uint_as_float(hb);
    float r = x - hi;
    uint32_t lb;
    asm("cvt.rna.tf32.f32 %0, %1;" : "=r"(lb) : "f"(r));
    lo = __uint_as_float(lb);
}
__device__ __forceinline__ uint32_t smem_u32(const void* p) {
    uint32_t a;
    asm("{ .reg .u64 t; cvta.to.shared.u64 t, %1; cvt.u32.u64 %0, t; }" : "=r"(a) : "l"(p));
    return a;
}
__device__ __forceinline__ void cp_async16(uint32_t dst, const void* src) {
    asm volatile("cp.async.ca.shared.global [%0], [%1], 16;" :: "r"(dst), "l"(src));
}
__device__ __forceinline__ void cp_commit() { asm volatile("cp.async.commit_group;"); }
template<int N> __device__ __forceinline__ void cp_wait() {
    asm volatile("cp.async.wait_group %0;" :: "n"(N));
}
__device__ __forceinline__ void mma_tf32(float* c, uint32_t a0, uint32_t a1, uint32_t a2,
                                         uint32_t a3, uint32_t b0, uint32_t b1) {
    asm volatile(
        "mma.sync.aligned.m16n8k8.row.col.f32.tf32.tf32.f32 "
        "{%0,%1,%2,%3}, {%4,%5,%6,%7}, {%8,%9}, {%0,%1,%2,%3};"
        : "+f"(c[0]), "+f"(c[1]), "+f"(c[2]), "+f"(c[3])
        : "r"(a0), "r"(a1), "r"(a2), "r"(a3), "r"(b0), "r"(b1));
}

// ---------------- depthwise conv(k=3) + residual + BN + split3 -------------
__global__ void conv_bn_kernel(const float* __restrict__ x, const float* __restrict__ w,
                               const float* __restrict__ bg, const float* __restrict__ bb,
                               const float* __restrict__ bm, const float* __restrict__ bv)
{
    int idx = blockIdx.x * blockDim.x + threadIdx.x;
    int d = idx & (D_ - 1);
    int t = idx >> 12;
    float xc = x[idx];
    float xm = (t > 0)      ? x[idx - BD_] : 0.f;
    float xp = (t < T_ - 1) ? x[idx + BD_] : 0.f;
    float y = fmaf(xm, w[d*3+0], fmaf(xc, w[d*3+1], fmaf(xp, w[d*3+2], xc)));
    y = (y - bm[d]) * rsqrtf(bv[d] + 1e-5f) * bg[d] + bb[d];
    g_xc[idx] = y;
    float hi, lo;
    tf32_split(y, hi, lo);
    size_t r3 = (size_t)(idx >> 9) * K3D + d;   // row = idx/D_
    g_xc3[r3]            = hi;      // A pattern: [hi, hi, lo]
    g_xc3[r3 + D_]       = hi;
    g_xc3[r3 + 2*D_]     = lo;
}

// ------- weight transpose + split: Wt3[n][3K] from W[K,N] ------------------
// B pattern: [hi, lo, hi]
__global__ __launch_bounds__(256) void transpose_split_kernel(const float* __restrict__ W,
                                                              float* __restrict__ Wt3,
                                                              int K, int N)
{
    __shared__ float tile[32][33];
    int k0 = blockIdx.y * 32, n0 = blockIdx.x * 32;
    int tx = threadIdx.x & 31, ty = threadIdx.x >> 5;
#pragma unroll
    for (int i = 0; i < 32; i += 8)
        tile[ty + i][tx] = W[(size_t)(k0 + ty + i) * N + n0 + tx];
    __syncthreads();
    int K3 = 3 * K;
#pragma unroll
    for (int i = 0; i < 32; i += 8) {
        float v = tile[tx][ty + i];
        float hi, lo;
        tf32_split(v, hi, lo);
        size_t base = (size_t)(n0 + ty + i) * K3 + k0 + tx;
        Wt3[base]         = hi;
        Wt3[base + K]     = lo;
        Wt3[base + 2*K]   = hi;
    }
}

// ================= plain tf32 mma.sync GEMM over 3K ========================
// C[M,N] = A3[M,K3] @ B3[N,K3]^T
// grid(N/128, M/128), 256 threads, BM=BN=128, BK=32, double-buffered cp.async.
// act: 0 = bias, 1 = gelu(acc+bias). res != null -> += res.
// osplit: 0 -> C[row*N+col];  1 -> C3[row*3N + {0,N,2N} + col] = {hi,hi,lo}.

#define TSTR 36
#define TILE_FLOATS (128 * TSTR)
#define GEMM_SMEM (2 * 2 * TILE_FLOATS * 4)

__device__ __forceinline__ void tile_prefetch(const float* __restrict__ g, int ldk,
                                              uint32_t sdst, int tid) {
#pragma unroll
    for (int i = 0; i < 4; i++) {
        int fi = i * 256 + tid;
        int r  = fi >> 3;
        int c4 = (fi & 7) * 4;
        cp_async16(sdst + (r * TSTR + c4) * 4, g + (size_t)r * ldk + c4);
    }
}

__global__ __launch_bounds__(256, 2) void tf32_gemm_kernel(
    const float* __restrict__ A, const float* __restrict__ Wt,
    const float* __restrict__ bias, const float* __restrict__ res,
    float* __restrict__ C, int M, int N, int K3, int act, int osplit)
{
    extern __shared__ float smem[];
    float* As[2] = { smem,               smem + 2 * TILE_FLOATS };
    float* Bs[2] = { smem + TILE_FLOATS, smem + 3 * TILE_FLOATS };

    const int tid  = threadIdx.x;
    const int wid  = tid >> 5, lane = tid & 31;
    const int wm   = (wid & 1) * 64;
    const int wn   = (wid >> 1) * 32;
    const int lr   = lane >> 2;
    const int lc   = lane & 3;
    const int bm   = blockIdx.y * 128, bn = blockIdx.x * 128;

    const float* Ab = A  + (size_t)bm * K3;
    const float* Bb = Wt + (size_t)bn * K3;
    const int NC = K3 >> 5;

    float acc[4][4][4];
#pragma unroll
    for (int mt = 0; mt < 4; mt++)
#pragma unroll
        for (int nt = 0; nt < 4; nt++)
#pragma unroll
            for (int j = 0; j < 4; j++) acc[mt][nt][j] = 0.f;

    uint32_t sA[2] = { smem_u32(As[0]), smem_u32(As[1]) };
    uint32_t sB[2] = { smem_u32(Bs[0]), smem_u32(Bs[1]) };

    tile_prefetch(Ab, K3, sA[0], tid);
    tile_prefetch(Bb, K3, sB[0], tid);
    cp_commit();

    for (int i = 0; i < NC; i++) {
        const int s = i & 1;
        if (i + 1 < NC) {
            tile_prefetch(Ab + (i + 1) * 32, K3, sA[s ^ 1], tid);
            tile_prefetch(Bb + (i + 1) * 32, K3, sB[s ^ 1], tid);
            cp_commit();
            cp_wait<1>();
        } else {
            cp_wait<0>();
        }
        __syncthreads();

        const float* a = As[s];
        const float* b = Bs[s];
#pragma unroll
        for (int ks = 0; ks < 4; ks++) {
            const int kc = ks * 8 + lc;
            uint32_t af[4][4], bf[4][2];
#pragma unroll
            for (int mt = 0; mt < 4; mt++) {
                const int r0 = wm + mt * 16 + lr;
                af[mt][0] = __float_as_uint(a[r0 * TSTR + kc]);
                af[mt][1] = __float_as_uint(a[(r0 + 8) * TSTR + kc]);
                af[mt][2] = __float_as_uint(a[r0 * TSTR + kc + 4]);
                af[mt][3] = __float_as_uint(a[(r0 + 8) * TSTR + kc + 4]);
            }
#pragma unroll
            for (int nt = 0; nt < 4; nt++) {
                const int n0 = wn + nt * 8 + lr;
                bf[nt][0] = __float_as_uint(b[n0 * TSTR + kc]);
                bf[nt][1] = __float_as_uint(b[n0 * TSTR + kc + 4]);
            }
#pragma unroll
            for (int mt = 0; mt < 4; mt++)
#pragma unroll
                for (int nt = 0; nt < 4; nt++)
                    mma_tf32(acc[mt][nt], af[mt][0], af[mt][1], af[mt][2], af[mt][3],
                             bf[nt][0], bf[nt][1]);
        }
        __syncthreads();
    }

    // ------- epilogue -------
#pragma unroll
    for (int mt = 0; mt < 4; mt++) {
        const int row0 = bm + wm + mt * 16 + lr;
#pragma unroll
        for (int nt = 0; nt < 4; nt++) {
            const int col = bn + wn + nt * 8 + lc * 2;
            const float bi0 = bias[col], bi1 = bias[col + 1];
#pragma unroll
            for (int half = 0; half < 2; half++) {
                const int row = row0 + half * 8;
                float v0 = acc[mt][nt][half * 2 + 0] + bi0;
                float v1 = acc[mt][nt][half * 2 + 1] + bi1;
                if (act == 1) {
                    v0 = 0.5f * v0 * (1.f + erff(v0 * 0.7071067811865475f));
                    v1 = 0.5f * v1 * (1.f + erff(v1 * 0.7071067811865475f));
                }
                if (res) {
                    float2 r2 = *(const float2*)(res + (size_t)row * N + col);
                    v0 += r2.x; v1 += r2.y;
                }
                if (osplit) {
                    float h0, l0, h1, l1;
                    tf32_split(v0, h0, l0);
                    tf32_split(v1, h1, l1);
                    float* p = C + (size_t)row * (3 * N) + col;
                    *(float2*)(p)         = make_float2(h0, h1);   // seg0 hi
                    *(float2*)(p + N)     = make_float2(h0, h1);   // seg1 hi
                    *(float2*)(p + 2 * N) = make_float2(l0, l1);   // seg2 lo
                } else {
                    *(float2*)(C + (size_t)row * N + col) = make_float2(v0, v1);
                }
            }
        }
    }
}

// ---------------- bucketed sparse attention (split3 output) ----------------
#define QS_STRIDE 68
#define WS_STRIDE 132
#define ATTN_SMEM ((64*QS_STRIDE + 128*QS_STRIDE + 128*QS_STRIDE + 64*WS_STRIDE) * 4)

__global__ __launch_bounds__(256) void attn_kernel(
    const float* __restrict__ Q, const float* __restrict__ Kt, const float* __restrict__ V,
    const int* __restrict__ t_length, const int* __restrict__ rand_idx,
    float* __restrict__ O3)
{
    extern __shared__ float sm[];
    float* qs = sm;
    float* ks = qs + 64 * QS_STRIDE;
    float* vs = ks + 128 * QS_STRIDE;
    float* ws = vs + 128 * QS_STRIDE;

    const int nb = blockIdx.x, h = blockIdx.y, b = blockIdx.z;
    const int tid = threadIdx.x;
    const int lane = tid & 31, warp = tid >> 5;
    const int t0 = nb * BS_;
    const int rb = rand_idx[nb];
    const int tlen = t_length[b];
    const int base = b * D_ + h * DH_;

#pragma unroll
    for (int i = 0; i < 4; i++) {
        int idx = i * 256 + tid;
        int r = idx >> 4;
        int c4 = (idx & 15) << 2;
        *(float4*)&qs[r * QS_STRIDE + c4] =
            *(const float4*)(Q + (size_t)(t0 + r) * BD_ + base + c4);
    }
#pragma unroll
    for (int i = 0; i < 8; i++) {
        int idx = i * 256 + tid;
        int r = idx >> 4;
        int c4 = (idx & 15) << 2;
        int t = (r < 64) ? (t0 + r) : (rb * BS_ + r - 64);
        *(float4*)&ks[r * QS_STRIDE + c4] =
            *(const float4*)(Kt + (size_t)t * BD_ + base + c4);
        *(float4*)&vs[r * QS_STRIDE + c4] =
            *(const float4*)(V + (size_t)t * BD_ + base + c4);
    }
    __syncthreads();

    const int r0 = warp * 8;
    float acc[8][4];
#pragma unroll
    for (int r = 0; r < 8; r++)
#pragma unroll
        for (int c = 0; c < 4; c++) acc[r][c] = 0.f;

#pragma unroll
    for (int k4 = 0; k4 < 16; k4++) {
        float4 kk[4];
#pragma unroll
        for (int c = 0; c < 4; c++)
            kk[c] = *(const float4*)&ks[(c * 32 + lane) * QS_STRIDE + k4 * 4];
#pragma unroll
        for (int r = 0; r < 8; r++) {
            float4 qv = *(const float4*)&qs[(r0 + r) * QS_STRIDE + k4 * 4];
#pragma unroll
            for (int c = 0; c < 4; c++) {
                acc[r][c] = fmaf(qv.x, kk[c].x, acc[r][c]);
                acc[r][c] = fmaf(qv.y, kk[c].y, acc[r][c]);
                acc[r][c] = fmaf(qv.z, kk[c].z, acc[r][c]);
                acc[r][c] = fmaf(qv.w, kk[c].w, acc[r][c]);
            }
        }
    }

    bool msk[4];
#pragma unroll
    for (int c = 0; c < 4; c++) {
        int jc = c * 32 + lane;
        int kp = (jc < 64) ? (t0 + jc) : (rb * BS_ + jc - 64);
        msk[c] = kp >= tlen;
    }

#pragma unroll
    for (int r = 0; r < 8; r++) {
        float s[4];
        float mx = -1e30f;
#pragma unroll
        for (int c = 0; c < 4; c++) {
            s[c] = msk[c] ? -1e9f : acc[r][c] * 0.125f;
            mx = fmaxf(mx, s[c]);
        }
#pragma unroll
        for (int off = 16; off; off >>= 1)
            mx = fmaxf(mx, __shfl_xor_sync(0xffffffffu, mx, off));
        float e[4], sum = 0.f;
#pragma unroll
        for (int c = 0; c < 4; c++) { e[c] = __expf(s[c] - mx); sum += e[c]; }
#pragma unroll
        for (int off = 16; off; off >>= 1)
            sum += __shfl_xor_sync(0xffffffffu, sum, off);
        float inv = 1.f / sum;
#pragma unroll
        for (int c = 0; c < 4; c++)
            ws[(r0 + r) * WS_STRIDE + c * 32 + lane] = e[c] * inv;
    }
    __syncwarp();

    float acc2[8][2];
#pragma unroll
    for (int r = 0; r < 8; r++) { acc2[r][0] = 0.f; acc2[r][1] = 0.f; }

#pragma unroll
    for (int j4 = 0; j4 < 32; j4++) {
        int j = j4 * 4;
        float vv[4][2];
#pragma unroll
        for (int jj = 0; jj < 4; jj++) {
#pragma unroll
            for (int c = 0; c < 2; c++)
                vv[jj][c] = vs[(j + jj) * QS_STRIDE + c * 32 + lane];
        }
#pragma unroll
        for (int r = 0; r < 8; r++) {
            float4 w4 = *(const float4*)&ws[(r0 + r) * WS_STRIDE + j];
#pragma unroll
            for (int c = 0; c < 2; c++) {
                acc2[r][c] = fmaf(w4.x, vv[0][c], acc2[r][c]);
                acc2[r][c] = fmaf(w4.y, vv[1][c], acc2[r][c]);
                acc2[r][c] = fmaf(w4.z, vv[2][c], acc2[r][c]);
                acc2[r][c] = fmaf(w4.w, vv[3][c], acc2[r][c]);
            }
        }
    }

    // split3 store: row = t*B_+b, col = h*DH + c*32+lane, pattern [hi,hi,lo]
#pragma unroll
    for (int r = 0; r < 8; r++)
#pragma unroll
        for (int c = 0; c < 2; c++) {
            float hi, lo;
            tf32_split(acc2[r][c], hi, lo);
            size_t rowb = (size_t)((t0 + r0 + r) * B_ + b) * K3D + h * DH_ + c * 32 + lane;
            O3[rowb]          = hi;
            O3[rowb + D_]     = hi;
            O3[rowb + 2*D_]   = lo;
        }
}

// ---------------- LayerNorm (+ optional split3 out) ------------------------
__global__ __launch_bounds__(128) void ln_kernel(const float* __restrict__ in,
    const float* __restrict__ g, const float* __restrict__ bta,
    float* __restrict__ out, float* __restrict__ out3)
{
    int row = blockIdx.x;
    int tid = threadIdx.x;
    const float* p = in + (size_t)row * D_;
    float4 v = *(const float4*)(p + tid * 4);
    float s  = v.x + v.y + v.z + v.w;
    float ss = v.x * v.x + v.y * v.y + v.z * v.z + v.w * v.w;
#pragma unroll
    for (int off = 16; off; off >>= 1) {
        s  += __shfl_xor_sync(0xffffffffu, s,  off);
        ss += __shfl_xor_sync(0xffffffffu, ss, off);
    }
    __shared__ float sb[8];
    int w = tid >> 5;
    if ((tid & 31) == 0) { sb[w] = s; sb[4 + w] = ss; }
    __syncthreads();
    s  = sb[0] + sb[1] + sb[2] + sb[3];
    ss = sb[4] + sb[5] + sb[6] + sb[7];
    float mean = s * (1.f / D_);
    float var  = ss * (1.f / D_) - mean * mean;
    float inv  = rsqrtf(var + 1e-5f);
    float4 g4 = *(const float4*)(g + tid * 4);
    float4 b4 = *(const float4*)(bta + tid * 4);
    float4 o;
    o.x = (v.x - mean) * inv * g4.x + b4.x;
    o.y = (v.y - mean) * inv * g4.y + b4.y;
    o.z = (v.z - mean) * inv * g4.z + b4.z;
    o.w = (v.w - mean) * inv * g4.w + b4.w;
    *(float4*)(out + (size_t)row * D_ + tid * 4) = o;
    if (out3) {
        float4 h4, l4;
        tf32_split(o.x, h4.x, l4.x);
        tf32_split(o.y, h4.y, l4.y);
        tf32_split(o.z, h4.z, l4.z);
        tf32_split(o.w, h4.w, l4.w);
        float* q = out3 + (size_t)row * K3D + tid * 4;
        *(float4*)(q)          = h4;
        *(float4*)(q + D_)     = h4;
        *(float4*)(q + 2*D_)   = l4;
    }
}

// ---------------- launch ---------------------------------------------------
extern "C" void kernel_launch(void* const* d_in, const int* in_sizes, int n_in,
                              void* d_out, int out_size)
{
    const float* x      = (const float*)d_in[0];
    const int*   t_len  = (const int*)d_in[1];
    const int*   ridx   = (const int*)d_in[2];
    const float* conv_w = (const float*)d_in[3];
    const float* bn_g   = (const float*)d_in[4];
    const float* bn_b   = (const float*)d_in[5];
    const float* bn_m   = (const float*)d_in[6];
    const float* bn_v   = (const float*)d_in[7];
    const float* wq = (const float*)d_in[8];  const float* bq = (const float*)d_in[9];
    const float* wk = (const float*)d_in[10]; const float* bk = (const float*)d_in[11];
    const float* wv = (const float*)d_in[12]; const float* bv = (const float*)d_in[13];
    const float* wo = (const float*)d_in[14]; const float* bo = (const float*)d_in[15];
    const float* ln1g = (const float*)d_in[16]; const float* ln1b = (const float*)d_in[17];
    const float* w1 = (const float*)d_in[18]; const float* b1 = (const float*)d_in[19];
    const float* w2 = (const float*)d_in[20]; const float* b2 = (const float*)d_in[21];
    const float* ln2g = (const float*)d_in[22]; const float* ln2b = (const float*)d_in[23];
    float* out = (float*)d_out;

    float *xc, *xc3, *attn3, *hbuf3, *q, *k, *v, *x1, *tmp;
    float *wt3q, *wt3k, *wt3v, *wt3o, *wt31, *wt32;
    cudaGetSymbolAddress((void**)&xc,    g_xc);
    cudaGetSymbolAddress((void**)&xc3,   g_xc3);
    cudaGetSymbolAddress((void**)&attn3, g_attn3);
    cudaGetSymbolAddress((void**)&hbuf3, g_hbuf3);
    cudaGetSymbolAddress((void**)&q,     g_q);
    cudaGetSymbolAddress((void**)&k,     g_k);
    cudaGetSymbolAddress((void**)&v,     g_v);
    cudaGetSymbolAddress((void**)&x1,    g_x1);
    cudaGetSymbolAddress((void**)&tmp,   g_tmp);
    cudaGetSymbolAddress((void**)&wt3q,  g_wt3q);
    cudaGetSymbolAddress((void**)&wt3k,  g_wt3k);
    cudaGetSymbolAddress((void**)&wt3v,  g_wt3v);
    cudaGetSymbolAddress((void**)&wt3o,  g_wt3o);
    cudaGetSymbolAddress((void**)&wt31,  g_wt31);
    cudaGetSymbolAddress((void**)&wt32,  g_wt32);

    cudaFuncSetAttribute(attn_kernel, cudaFuncAttributeMaxDynamicSharedMemorySize, ATTN_SMEM);
    cudaFuncSetAttribute(tf32_gemm_kernel, cudaFuncAttributeMaxDynamicSharedMemorySize, GEMM_SMEM);

    // 0. weight transpose+split ([K,N] -> [N,3K])
    transpose_split_kernel<<<dim3(D_/32, D_/32), 256>>>(wq, wt3q, D_, D_);
    transpose_split_kernel<<<dim3(D_/32, D_/32), 256>>>(wk, wt3k, D_, D_);
    transpose_split_kernel<<<dim3(D_/32, D_/32), 256>>>(wv, wt3v, D_, D_);
    transpose_split_kernel<<<dim3(D_/32, D_/32), 256>>>(wo, wt3o, D_, D_);
    transpose_split_kernel<<<dim3(2*D_/32, D_/32), 256>>>(w1, wt31, D_, 2*D_);
    transpose_split_kernel<<<dim3(D_/32, 2*D_/32), 256>>>(w2, wt32, 2*D_, D_);

    // 1. conv + residual + BN (+ split3)
    conv_bn_kernel<<<(M_ * D_) / 256, 256>>>(x, conv_w, bn_g, bn_b, bn_m, bn_v);

    // 2. Q/K/V projections
    dim3 g512(D_ / 128, M_ / 128);       // (4, 256)
    tf32_gemm_kernel<<<g512, 256, GEMM_SMEM>>>(xc3, wt3q, bq, nullptr, q, M_, D_, K3D, 0, 0);
    tf32_gemm_kernel<<<g512, 256, GEMM_SMEM>>>(xc3, wt3k, bk, nullptr, k, M_, D_, K3D, 0, 0);
    tf32_gemm_kernel<<<g512, 256, GEMM_SMEM>>>(xc3, wt3v, bv, nullptr, v, M_, D_, K3D, 0, 0);

    // 3. bucketed sparse attention (-> attn3 split)
    attn_kernel<<<dim3(NB_, H_, B_), 256, ATTN_SMEM>>>(q, k, v, t_len, ridx, attn3);

    // 4. output projection + bias + residual(xc), then LN1 (+x13 split into xc3)
    tf32_gemm_kernel<<<g512, 256, GEMM_SMEM>>>(attn3, wt3o, bo, xc, tmp, M_, D_, K3D, 0, 0);
    ln_kernel<<<M_, 128>>>(tmp, ln1g, ln1b, x1, xc3);

    // 5. MLP: gelu(x1@w1+b1) -> hbuf3 (split), @w2 + b2 + x1, LN2 -> out
    dim3 g1024(2 * D_ / 128, M_ / 128);  // (8, 256)
    tf32_gemm_kernel<<<g1024, 256, GEMM_SMEM>>>(xc3, wt31, b1, nullptr, hbuf3, M_, 2 * D_, K3D, 1, 1);
    tf32_gemm_kernel<<<g512, 256, GEMM_SMEM>>>(hbuf3, wt32, b2, x1, tmp, M_, D_, K3H, 0, 0);
    ln_kernel<<<M_, 128>>>(tmp, ln2g, ln2b, out, nullptr);
}

// round 6
// speedup vs baseline: 1.8102x; 1.8102x over previous
#include <cuda_runtime.h>
#include <cuda_bf16.h>
#include <cstdint>
#include <math.h>

// Problem constants
#define T_   4096
#define B_   8
#define D_   512
#define H_   8
#define BS_  64
#define NB_  64
#define DH_  64
#define M_   (T_*B_)    // 32768 rows
#define BD_  (B_*D_)    // 4096
#define K3D  (3*D_)     // 1536
#define K3H  (3*2*D_)   // 3072

// ---------------- scratch (static device globals; no allocations) ----------
__device__ float g_xc [M_*D_];                 // conv+bn output (residual)
__device__ __nv_bfloat16 g_xc3  [M_*K3D];      // [hi,hi,lo] of xc; reused for x1
__device__ __nv_bfloat16 g_attn3[M_*K3D];      // [hi,hi,lo] of attention out
__device__ __nv_bfloat16 g_hbuf3[(size_t)M_*K3H]; // [hi,hi,lo] of gelu(MLP1)
__device__ float g_q  [M_*D_];
__device__ float g_k  [M_*D_];
__device__ float g_v  [M_*D_];
__device__ float g_x1 [M_*D_];
__device__ float g_tmp[M_*D_];
// transposed + split weights [N][3K], pattern [hi,lo,hi]
__device__ __nv_bfloat16 g_wt3q [D_*K3D];
__device__ __nv_bfloat16 g_wt3k [D_*K3D];
__device__ __nv_bfloat16 g_wt3v [D_*K3D];
__device__ __nv_bfloat16 g_wt3o [D_*K3D];
__device__ __nv_bfloat16 g_wt31 [2*D_*K3D];
__device__ __nv_bfloat16 g_wt32 [(size_t)D_*K3H];

// ---------------- helpers ---------------------------------------------------
__device__ __forceinline__ void bf16_split(float x, __nv_bfloat16& h, __nv_bfloat16& l) {
    h = __float2bfloat16_rn(x);
    l = __float2bfloat16_rn(x - __bfloat162float(h));
}
__device__ __forceinline__ uint32_t smem_u32(const void* p) {
    uint32_t a;
    asm("{ .reg .u64 t; cvta.to.shared.u64 t, %1; cvt.u32.u64 %0, t; }" : "=r"(a) : "l"(p));
    return a;
}
__device__ __forceinline__ void cp_async16(uint32_t dst, const void* src) {
    asm volatile("cp.async.ca.shared.global [%0], [%1], 16;" :: "r"(dst), "l"(src));
}
__device__ __forceinline__ void cp_commit() { asm volatile("cp.async.commit_group;"); }
template<int N> __device__ __forceinline__ void cp_wait() {
    asm volatile("cp.async.wait_group %0;" :: "n"(N));
}
#define LDSM4(r0, r1, r2, r3, addr) \
    asm volatile("ldmatrix.sync.aligned.m8n8.x4.shared.b16 {%0,%1,%2,%3}, [%4];" \
        : "=r"(r0), "=r"(r1), "=r"(r2), "=r"(r3) : "r"(addr))
__device__ __forceinline__ void mma_bf16(float* c, const uint32_t* a, uint32_t b0, uint32_t b1) {
    asm volatile(
        "mma.sync.aligned.m16n8k16.row.col.f32.bf16.bf16.f32 "
        "{%0,%1,%2,%3}, {%4,%5,%6,%7}, {%8,%9}, {%0,%1,%2,%3};"
        : "+f"(c[0]), "+f"(c[1]), "+f"(c[2]), "+f"(c[3])
        : "r"(a[0]), "r"(a[1]), "r"(a[2]), "r"(a[3]), "r"(b0), "r"(b1));
}

// ---------------- depthwise conv(k=3) + residual + BN + bf16 split3 --------
__global__ void conv_bn_kernel(const float* __restrict__ x, const float* __restrict__ w,
                               const float* __restrict__ bg, const float* __restrict__ bb,
                               const float* __restrict__ bm, const float* __restrict__ bv)
{
    int idx = blockIdx.x * blockDim.x + threadIdx.x;
    int d = idx & (D_ - 1);
    int t = idx >> 12;
    float xc = x[idx];
    float xm = (t > 0)      ? x[idx - BD_] : 0.f;
    float xp = (t < T_ - 1) ? x[idx + BD_] : 0.f;
    float y = fmaf(xm, w[d*3+0], fmaf(xc, w[d*3+1], fmaf(xp, w[d*3+2], xc)));
    y = (y - bm[d]) * rsqrtf(bv[d] + 1e-5f) * bg[d] + bb[d];
    g_xc[idx] = y;
    __nv_bfloat16 hi, lo;
    bf16_split(y, hi, lo);
    size_t r3 = (size_t)(idx >> 9) * K3D + d;   // row = t*B_+b
    g_xc3[r3]          = hi;    // A pattern [hi, hi, lo]
    g_xc3[r3 + D_]     = hi;
    g_xc3[r3 + 2*D_]   = lo;
}

// ------- weight transpose + split: Wt3[n][3K] bf16 from W[K,N] -------------
// B pattern: [hi, lo, hi]
__global__ __launch_bounds__(256) void transpose_split_kernel(const float* __restrict__ W,
                                                              __nv_bfloat16* __restrict__ Wt3,
                                                              int K, int N)
{
    __shared__ float tile[32][33];
    int k0 = blockIdx.y * 32, n0 = blockIdx.x * 32;
    int tx = threadIdx.x & 31, ty = threadIdx.x >> 5;
#pragma unroll
    for (int i = 0; i < 32; i += 8)
        tile[ty + i][tx] = W[(size_t)(k0 + ty + i) * N + n0 + tx];
    __syncthreads();
    int K3 = 3 * K;
#pragma unroll
    for (int i = 0; i < 32; i += 8) {
        float v = tile[tx][ty + i];
        __nv_bfloat16 hi, lo;
        bf16_split(v, hi, lo);
        size_t base = (size_t)(n0 + ty + i) * K3 + k0 + tx;
        Wt3[base]         = hi;
        Wt3[base + K]     = lo;
        Wt3[base + 2*K]   = hi;
    }
}

// ================= bf16 3K mma.sync GEMM (ldmatrix path) ====================
// C[M,N] = A3[M,K3] @ B3[N,K3]^T  (both bf16 row-major)
// grid(N/128, M/128), 256 threads, BM=BN=128, BK=32, double-buffered cp.async.
// smem tile: 128 rows x 64B data @ 80B stride (5x16B -> LDSM conflict-free).
// act: 0 = bias, 1 = gelu(acc+bias). res != null -> += res (fp32).
// osplit: 0 -> fp32 C[row*N+col]; 1 -> bf16 C3[row*3N + {0,N,2N} + col] = {hi,hi,lo}.

#define ROWB   80
#define STAGEB (128 * ROWB)          // 10240 bytes per operand tile
#define GEMM_SMEM (2 * 2 * STAGEB)   // 2 stages x (A,B) = 40960 bytes

__device__ __forceinline__ void stage_prefetch(const __nv_bfloat16* __restrict__ Ab,
                                               const __nv_bfloat16* __restrict__ Bb,
                                               int K3, int chunk, uint32_t sbase, int tid)
{
#pragma unroll
    for (int i = 0; i < 4; i++) {
        int slot = i * 256 + tid;            // 0..1023
        int isB  = slot >> 9;                // 0 = A, 1 = B
        int s2   = slot & 511;
        int row  = s2 >> 2;                  // 0..127
        int c    = s2 & 3;                   // 16B column block
        const __nv_bfloat16* src = (isB ? Bb : Ab) + (size_t)row * K3 + chunk * 32 + c * 8;
        uint32_t dst = sbase + isB * STAGEB + row * ROWB + c * 16;
        cp_async16(dst, src);
    }
}

__global__ __launch_bounds__(256, 2) void bf16_gemm_kernel(
    const __nv_bfloat16* __restrict__ A, const __nv_bfloat16* __restrict__ Wt,
    const float* __restrict__ bias, const float* __restrict__ res,
    void* __restrict__ Cout, int M, int N, int K3, int act, int osplit)
{
    extern __shared__ char smem[];
    const uint32_t sb0 = smem_u32(smem);

    const int tid  = threadIdx.x;
    const int wid  = tid >> 5, lane = tid & 31;
    const int wm   = (wid & 1) * 64;
    const int wn   = (wid >> 1) * 32;
    const int lr   = lane >> 2;
    const int lc   = lane & 3;
    const int bm   = blockIdx.y * 128, bn = blockIdx.x * 128;

    const __nv_bfloat16* Ab = A  + (size_t)bm * K3;
    const __nv_bfloat16* Bb = Wt + (size_t)bn * K3;
    const int NC = K3 >> 5;

    float acc[4][4][4];
#pragma unroll
    for (int mt = 0; mt < 4; mt++)
#pragma unroll
        for (int nt = 0; nt < 4; nt++)
#pragma unroll
            for (int j = 0; j < 4; j++) acc[mt][nt][j] = 0.f;

    // LDSM source addresses: row = base + (lane&15), col block = +(lane>>4)
    const int lrow = lane & 15;
    const int lcb  = lane >> 4;

    stage_prefetch(Ab, Bb, K3, 0, sb0, tid);
    cp_commit();

    for (int i = 0; i < NC; i++) {
        const int s = i & 1;
        cp_wait<0>();
        __syncthreads();
        if (i + 1 < NC) {
            stage_prefetch(Ab, Bb, K3, i + 1, sb0 + (s ^ 1) * (2 * STAGEB), tid);
            cp_commit();
        }
        const uint32_t aS = sb0 + s * (2 * STAGEB);
        const uint32_t bS = aS + STAGEB;
#pragma unroll
        for (int ks = 0; ks < 2; ks++) {
            uint32_t afr[4][4];
#pragma unroll
            for (int mt = 0; mt < 4; mt++) {
                uint32_t ad = aS + (wm + mt * 16 + lrow) * ROWB + (ks * 2 + lcb) * 16;
                LDSM4(afr[mt][0], afr[mt][1], afr[mt][2], afr[mt][3], ad);
            }
            uint32_t bfr[4][2];
#pragma unroll
            for (int np = 0; np < 2; np++) {
                uint32_t bd = bS + (wn + np * 16 + lrow) * ROWB + (ks * 2 + lcb) * 16;
                uint32_t r0, r1, r2, r3;
                LDSM4(r0, r1, r2, r3, bd);
                bfr[np * 2][0] = r0; bfr[np * 2 + 1][0] = r1;
                bfr[np * 2][1] = r2; bfr[np * 2 + 1][1] = r3;
            }
#pragma unroll
            for (int mt = 0; mt < 4; mt++)
#pragma unroll
                for (int nt = 0; nt < 4; nt++)
                    mma_bf16(acc[mt][nt], afr[mt], bfr[nt][0], bfr[nt][1]);
        }
        __syncthreads();
    }

    // ------- epilogue -------
#pragma unroll
    for (int mt = 0; mt < 4; mt++) {
        const int row0 = bm + wm + mt * 16 + lr;
#pragma unroll
        for (int nt = 0; nt < 4; nt++) {
            const int col = bn + wn + nt * 8 + lc * 2;
            const float bi0 = bias[col], bi1 = bias[col + 1];
#pragma unroll
            for (int half = 0; half < 2; half++) {
                const int row = row0 + half * 8;
                float v0 = acc[mt][nt][half * 2 + 0] + bi0;
                float v1 = acc[mt][nt][half * 2 + 1] + bi1;
                if (act == 1) {
                    v0 = 0.5f * v0 * (1.f + erff(v0 * 0.7071067811865475f));
                    v1 = 0.5f * v1 * (1.f + erff(v1 * 0.7071067811865475f));
                }
                if (res) {
                    float2 r2 = *(const float2*)(res + (size_t)row * N + col);
                    v0 += r2.x; v1 += r2.y;
                }
                if (osplit) {
                    __nv_bfloat16 h0, l0, h1, l1;
                    bf16_split(v0, h0, l0);
                    bf16_split(v1, h1, l1);
                    __nv_bfloat16* p = (__nv_bfloat16*)Cout + (size_t)row * (3 * N) + col;
                    *(__nv_bfloat162*)(p)         = __nv_bfloat162(h0, h1);  // seg0 hi
                    *(__nv_bfloat162*)(p + N)     = __nv_bfloat162(h0, h1);  // seg1 hi
                    *(__nv_bfloat162*)(p + 2 * N) = __nv_bfloat162(l0, l1);  // seg2 lo
                } else {
                    *(float2*)((float*)Cout + (size_t)row * N + col) = make_float2(v0, v1);
                }
            }
        }
    }
}

// ---------------- bucketed sparse attention (bf16 split3 output) -----------
#define QS_STRIDE 68
#define WS_STRIDE 132
#define ATTN_SMEM ((64*QS_STRIDE + 128*QS_STRIDE + 128*QS_STRIDE + 64*WS_STRIDE) * 4)

__global__ __launch_bounds__(256) void attn_kernel(
    const float* __restrict__ Q, const float* __restrict__ Kt, const float* __restrict__ V,
    const int* __restrict__ t_length, const int* __restrict__ rand_idx,
    __nv_bfloat16* __restrict__ O3)
{
    extern __shared__ float sm[];
    float* qs = sm;
    float* ks = qs + 64 * QS_STRIDE;
    float* vs = ks + 128 * QS_STRIDE;
    float* ws = vs + 128 * QS_STRIDE;

    const int nb = blockIdx.x, h = blockIdx.y, b = blockIdx.z;
    const int tid = threadIdx.x;
    const int lane = tid & 31, warp = tid >> 5;
    const int t0 = nb * BS_;
    const int rb = rand_idx[nb];
    const int tlen = t_length[b];
    const int base = b * D_ + h * DH_;

#pragma unroll
    for (int i = 0; i < 4; i++) {
        int idx = i * 256 + tid;
        int r = idx >> 4;
        int c4 = (idx & 15) << 2;
        *(float4*)&qs[r * QS_STRIDE + c4] =
            *(const float4*)(Q + (size_t)(t0 + r) * BD_ + base + c4);
    }
#pragma unroll
    for (int i = 0; i < 8; i++) {
        int idx = i * 256 + tid;
        int r = idx >> 4;
        int c4 = (idx & 15) << 2;
        int t = (r < 64) ? (t0 + r) : (rb * BS_ + r - 64);
        *(float4*)&ks[r * QS_STRIDE + c4] =
            *(const float4*)(Kt + (size_t)t * BD_ + base + c4);
        *(float4*)&vs[r * QS_STRIDE + c4] =
            *(const float4*)(V + (size_t)t * BD_ + base + c4);
    }
    __syncthreads();

    const int r0 = warp * 8;
    float acc[8][4];
#pragma unroll
    for (int r = 0; r < 8; r++)
#pragma unroll
        for (int c = 0; c < 4; c++) acc[r][c] = 0.f;

#pragma unroll
    for (int k4 = 0; k4 < 16; k4++) {
        float4 kk[4];
#pragma unroll
        for (int c = 0; c < 4; c++)
            kk[c] = *(const float4*)&ks[(c * 32 + lane) * QS_STRIDE + k4 * 4];
#pragma unroll
        for (int r = 0; r < 8; r++) {
            float4 qv = *(const float4*)&qs[(r0 + r) * QS_STRIDE + k4 * 4];
#pragma unroll
            for (int c = 0; c < 4; c++) {
                acc[r][c] = fmaf(qv.x, kk[c].x, acc[r][c]);
                acc[r][c] = fmaf(qv.y, kk[c].y, acc[r][c]);
                acc[r][c] = fmaf(qv.z, kk[c].z, acc[r][c]);
                acc[r][c] = fmaf(qv.w, kk[c].w, acc[r][c]);
            }
        }
    }

    bool msk[4];
#pragma unroll
    for (int c = 0; c < 4; c++) {
        int jc = c * 32 + lane;
        int kp = (jc < 64) ? (t0 + jc) : (rb * BS_ + jc - 64);
        msk[c] = kp >= tlen;
    }

#pragma unroll
    for (int r = 0; r < 8; r++) {
        float s[4];
        float mx = -1e30f;
#pragma unroll
        for (int c = 0; c < 4; c++) {
            s[c] = msk[c] ? -1e9f : acc[r][c] * 0.125f;
            mx = fmaxf(mx, s[c]);
        }
#pragma unroll
        for (int off = 16; off; off >>= 1)
            mx = fmaxf(mx, __shfl_xor_sync(0xffffffffu, mx, off));
        float e[4], sum = 0.f;
#pragma unroll
        for (int c = 0; c < 4; c++) { e[c] = __expf(s[c] - mx); sum += e[c]; }
#pragma unroll
        for (int off = 16; off; off >>= 1)
            sum += __shfl_xor_sync(0xffffffffu, sum, off);
        float inv = 1.f / sum;
#pragma unroll
        for (int c = 0; c < 4; c++)
            ws[(r0 + r) * WS_STRIDE + c * 32 + lane] = e[c] * inv;
    }
    __syncwarp();

    float acc2[8][2];
#pragma unroll
    for (int r = 0; r < 8; r++) { acc2[r][0] = 0.f; acc2[r][1] = 0.f; }

#pragma unroll
    for (int j4 = 0; j4 < 32; j4++) {
        int j = j4 * 4;
        float vv[4][2];
#pragma unroll
        for (int jj = 0; jj < 4; jj++) {
#pragma unroll
            for (int c = 0; c < 2; c++)
                vv[jj][c] = vs[(j + jj) * QS_STRIDE + c * 32 + lane];
        }
#pragma unroll
        for (int r = 0; r < 8; r++) {
            float4 w4 = *(const float4*)&ws[(r0 + r) * WS_STRIDE + j];
#pragma unroll
            for (int c = 0; c < 2; c++) {
                acc2[r][c] = fmaf(w4.x, vv[0][c], acc2[r][c]);
                acc2[r][c] = fmaf(w4.y, vv[1][c], acc2[r][c]);
                acc2[r][c] = fmaf(w4.z, vv[2][c], acc2[r][c]);
                acc2[r][c] = fmaf(w4.w, vv[3][c], acc2[r][c]);
            }
        }
    }

    // bf16 split3 store: row = t*B_+b, col = h*DH + c*32+lane, pattern [hi,hi,lo]
#pragma unroll
    for (int r = 0; r < 8; r++)
#pragma unroll
        for (int c = 0; c < 2; c++) {
            __nv_bfloat16 hi, lo;
            bf16_split(acc2[r][c], hi, lo);
            size_t rowb = (size_t)((t0 + r0 + r) * B_ + b) * K3D + h * DH_ + c * 32 + lane;
            O3[rowb]          = hi;
            O3[rowb + D_]     = hi;
            O3[rowb + 2*D_]   = lo;
        }
}

// ---------------- LayerNorm (+ optional bf16 split3 out) -------------------
__global__ __launch_bounds__(128) void ln_kernel(const float* __restrict__ in,
    const float* __restrict__ g, const float* __restrict__ bta,
    float* __restrict__ out, __nv_bfloat16* __restrict__ out3)
{
    int row = blockIdx.x;
    int tid = threadIdx.x;
    const float* p = in + (size_t)row * D_;
    float4 v = *(const float4*)(p + tid * 4);
    float s  = v.x + v.y + v.z + v.w;
    float ss = v.x * v.x + v.y * v.y + v.z * v.z + v.w * v.w;
#pragma unroll
    for (int off = 16; off; off >>= 1) {
        s  += __shfl_xor_sync(0xffffffffu, s,  off);
        ss += __shfl_xor_sync(0xffffffffu, ss, off);
    }
    __shared__ float sb[8];
    int w = tid >> 5;
    if ((tid & 31) == 0) { sb[w] = s; sb[4 + w] = ss; }
    __syncthreads();
    s  = sb[0] + sb[1] + sb[2] + sb[3];
    ss = sb[4] + sb[5] + sb[6] + sb[7];
    float mean = s * (1.f / D_);
    float var  = ss * (1.f / D_) - mean * mean;
    float inv  = rsqrtf(var + 1e-5f);
    float4 g4 = *(const float4*)(g + tid * 4);
    float4 b4 = *(const float4*)(bta + tid * 4);
    float4 o;
    o.x = (v.x - mean) * inv * g4.x + b4.x;
    o.y = (v.y - mean) * inv * g4.y + b4.y;
    o.z = (v.z - mean) * inv * g4.z + b4.z;
    o.w = (v.w - mean) * inv * g4.w + b4.w;
    *(float4*)(out + (size_t)row * D_ + tid * 4) = o;
    if (out3) {
        __nv_bfloat16 h[4], l[4];
        bf16_split(o.x, h[0], l[0]);
        bf16_split(o.y, h[1], l[1]);
        bf16_split(o.z, h[2], l[2]);
        bf16_split(o.w, h[3], l[3]);
        __nv_bfloat16* q = out3 + (size_t)row * K3D + tid * 4;
        *(__nv_bfloat162*)(q)            = __nv_bfloat162(h[0], h[1]);
        *(__nv_bfloat162*)(q + 2)        = __nv_bfloat162(h[2], h[3]);
        *(__nv_bfloat162*)(q + D_)       = __nv_bfloat162(h[0], h[1]);
        *(__nv_bfloat162*)(q + D_ + 2)   = __nv_bfloat162(h[2], h[3]);
        *(__nv_bfloat162*)(q + 2*D_)     = __nv_bfloat162(l[0], l[1]);
        *(__nv_bfloat162*)(q + 2*D_ + 2) = __nv_bfloat162(l[2], l[3]);
    }
}

// ---------------- launch ---------------------------------------------------
extern "C" void kernel_launch(void* const* d_in, const int* in_sizes, int n_in,
                              void* d_out, int out_size)
{
    const float* x      = (const float*)d_in[0];
    const int*   t_len  = (const int*)d_in[1];
    const int*   ridx   = (const int*)d_in[2];
    const float* conv_w = (const float*)d_in[3];
    const float* bn_g   = (const float*)d_in[4];
    const float* bn_b   = (const float*)d_in[5];
    const float* bn_m   = (const float*)d_in[6];
    const float* bn_v   = (const float*)d_in[7];
    const float* wq = (const float*)d_in[8];  const float* bq = (const float*)d_in[9];
    const float* wk = (const float*)d_in[10]; const float* bk = (const float*)d_in[11];
    const float* wv = (const float*)d_in[12]; const float* bv = (const float*)d_in[13];
    const float* wo = (const float*)d_in[14]; const float* bo = (const float*)d_in[15];
    const float* ln1g = (const float*)d_in[16]; const float* ln1b = (const float*)d_in[17];
    const float* w1 = (const float*)d_in[18]; const float* b1 = (const float*)d_in[19];
    const float* w2 = (const float*)d_in[20]; const float* b2 = (const float*)d_in[21];
    const float* ln2g = (const float*)d_in[22]; const float* ln2b = (const float*)d_in[23];
    float* out = (float*)d_out;

    float *xc, *q, *k, *v, *x1, *tmp;
    __nv_bfloat16 *xc3, *attn3, *hbuf3;
    __nv_bfloat16 *wt3q, *wt3k, *wt3v, *wt3o, *wt31, *wt32;
    cudaGetSymbolAddress((void**)&xc,    g_xc);
    cudaGetSymbolAddress((void**)&xc3,   g_xc3);
    cudaGetSymbolAddress((void**)&attn3, g_attn3);
    cudaGetSymbolAddress((void**)&hbuf3, g_hbuf3);
    cudaGetSymbolAddress((void**)&q,     g_q);
    cudaGetSymbolAddress((void**)&k,     g_k);
    cudaGetSymbolAddress((void**)&v,     g_v);
    cudaGetSymbolAddress((void**)&x1,    g_x1);
    cudaGetSymbolAddress((void**)&tmp,   g_tmp);
    cudaGetSymbolAddress((void**)&wt3q,  g_wt3q);
    cudaGetSymbolAddress((void**)&wt3k,  g_wt3k);
    cudaGetSymbolAddress((void**)&wt3v,  g_wt3v);
    cudaGetSymbolAddress((void**)&wt3o,  g_wt3o);
    cudaGetSymbolAddress((void**)&wt31,  g_wt31);
    cudaGetSymbolAddress((void**)&wt32,  g_wt32);

    cudaFuncSetAttribute(attn_kernel, cudaFuncAttributeMaxDynamicSharedMemorySize, ATTN_SMEM);
    cudaFuncSetAttribute(bf16_gemm_kernel, cudaFuncAttributeMaxDynamicSharedMemorySize, GEMM_SMEM);

    // 0. weight transpose+split ([K,N] -> [N,3K] bf16)
    transpose_split_kernel<<<dim3(D_/32, D_/32), 256>>>(wq, wt3q, D_, D_);
    transpose_split_kernel<<<dim3(D_/32, D_/32), 256>>>(wk, wt3k, D_, D_);
    transpose_split_kernel<<<dim3(D_/32, D_/32), 256>>>(wv, wt3v, D_, D_);
    transpose_split_kernel<<<dim3(D_/32, D_/32), 256>>>(wo, wt3o, D_, D_);
    transpose_split_kernel<<<dim3(2*D_/32, D_/32), 256>>>(w1, wt31, D_, 2*D_);
    transpose_split_kernel<<<dim3(D_/32, 2*D_/32), 256>>>(w2, wt32, 2*D_, D_);

    // 1. conv + residual + BN (+ bf16 split3)
    conv_bn_kernel<<<(M_ * D_) / 256, 256>>>(x, conv_w, bn_g, bn_b, bn_m, bn_v);

    // 2. Q/K/V projections (bf16 3-term mma.sync)
    dim3 g512(D_ / 128, M_ / 128);       // (4, 256)
    bf16_gemm_kernel<<<g512, 256, GEMM_SMEM>>>(xc3, wt3q, bq, nullptr, q, M_, D_, K3D, 0, 0);
    bf16_gemm_kernel<<<g512, 256, GEMM_SMEM>>>(xc3, wt3k, bk, nullptr, k, M_, D_, K3D, 0, 0);
    bf16_gemm_kernel<<<g512, 256, GEMM_SMEM>>>(xc3, wt3v, bv, nullptr, v, M_, D_, K3D, 0, 0);

    // 3. bucketed sparse attention (-> attn3 bf16 split)
    attn_kernel<<<dim3(NB_, H_, B_), 256, ATTN_SMEM>>>(q, k, v, t_len, ridx, attn3);

    // 4. output projection + bias + residual(xc), then LN1 (+x13 split into xc3)
    bf16_gemm_kernel<<<g512, 256, GEMM_SMEM>>>(attn3, wt3o, bo, xc, tmp, M_, D_, K3D, 0, 0);
    ln_kernel<<<M_, 128>>>(tmp, ln1g, ln1b, x1, xc3);

    // 5. MLP: gelu(x1@w1+b1) -> hbuf3 (bf16 split), @w2 + b2 + x1, LN2 -> out
    dim3 g1024(2 * D_ / 128, M_ / 128);  // (8, 256)
    bf16_gemm_kernel<<<g1024, 256, GEMM_SMEM>>>(xc3, wt31, b1, nullptr, hbuf3, M_, 2 * D_, K3D, 1, 1);
    bf16_gemm_kernel<<<g512, 256, GEMM_SMEM>>>(hbuf3, wt32, b2, x1, tmp, M_, D_, K3H, 0, 0);
    ln_kernel<<<M_, 128>>>(tmp, ln2g, ln2b, out, nullptr);
}